// round 1
// baseline (speedup 1.0000x reference)
#include <cuda_runtime.h>

// Problem geometry (fixed by the reference: B=16, C=3, H=W=512)
constexpr int BC   = 48;
constexpr int HW   = 512;
constexpr int L    = HW * HW;        // 262144 pixels per row
constexpr int NTOT = BC * L;         // 12,582,912
constexpr int WPL  = HW / 32;        // 16 words per image line
constexpr int WPI  = HW * WPL;       // 8192 words per image
constexpr int NW   = BC * WPI;       // 393,216 bitmask words

constexpr int CHUNK = 8192;          // pixels per block in count/scatter/loss
constexpr int CBLK  = L / CHUNK;     // 32 chunks per row
constexpr int NBLK  = BC * CBLK;     // 1536 blocks

// Scratch (device globals; no allocation allowed)
__device__ float    g_vpos[NTOT];
__device__ float    g_vfp [NTOT];
__device__ float    g_vneg[NTOT];
__device__ unsigned g_tbits[NW];
__device__ unsigned g_abits[NW];
__device__ int      g_ccnt[3][NBLK];
__device__ int      g_coff[3][NBLK];
__device__ int      g_rcnt[3][BC];
__device__ double   g_sum;

// ---------------------------------------------------------------- K1: pack t>0 bits
__global__ void k_pack(const float* __restrict__ tgt) {
    int i = blockIdx.x * 256 + threadIdx.x;
    unsigned b = __ballot_sync(0xffffffffu, tgt[i] > 0.f);
    if ((threadIdx.x & 31) == 0) g_tbits[i >> 5] = b;
}

// ------------------------------------------- K2: aug = clamped 7x7 OR of tbits
__global__ void k_aug() {
    int wi = blockIdx.x * 256 + threadIdx.x;
    if (wi >= NW) return;
    int img  = wi >> 13;          // / WPI
    int rem  = wi & (WPI - 1);
    int line = rem >> 4;          // / WPL
    int w    = rem & (WPL - 1);
    const unsigned* base = g_tbits + img * WPI;
    unsigned lo = 0, mid = 0, hi = 0;
    int l0 = line - 3 < 0 ? 0 : line - 3;
    int l1 = line + 3 > HW - 1 ? HW - 1 : line + 3;
    for (int l = l0; l <= l1; ++l) {
        const unsigned* p = base + l * WPL + w;
        mid |= p[0];
        if (w > 0)       lo |= p[-1];
        if (w < WPL - 1) hi |= p[1];
    }
    unsigned out = mid;
#pragma unroll
    for (int s = 1; s <= 3; ++s) {
        out |= __funnelshift_r(mid, hi, s);   // bits from higher pixels
        out |= __funnelshift_l(lo, mid, s);   // bits from lower pixels
    }
    g_abits[wi] = out;
}

// ---------------------------------------------------------------- K3: chunk counts
__global__ void k_count(const float* __restrict__ X) {
    int blk = blockIdx.x;
    int gbase = blk * CHUNK;
    int tid = threadIdx.x;
    unsigned long long pk = 0;  // pos | fp<<21 | neg<<42
    for (int it = 0; it < CHUNK / 256; ++it) {
        int g = gbase + it * 256 + tid;
        float x = X[g];
        unsigned tb = (g_tbits[g >> 5] >> (g & 31)) & 1u;
        unsigned ab = (g_abits[g >> 5] >> (g & 31)) & 1u;
        unsigned na = ab ^ 1u;
        unsigned fp = (x > 0.f) ? na : 0u;
        pk += (unsigned long long)tb
            | ((unsigned long long)fp << 21)
            | ((unsigned long long)na << 42);
    }
    __shared__ unsigned long long sh[8];
    int lane = tid & 31, warp = tid >> 5;
#pragma unroll
    for (int d = 16; d; d >>= 1) pk += __shfl_down_sync(0xffffffffu, pk, d);
    if (lane == 0) sh[warp] = pk;
    __syncthreads();
    if (warp == 0) {
        pk = (lane < 8) ? sh[lane] : 0ull;
#pragma unroll
        for (int d = 4; d; d >>= 1) pk += __shfl_down_sync(0xffffffffu, pk, d);
        if (lane == 0) {
            g_ccnt[0][blk] = (int)( pk        & 0x1FFFFF);
            g_ccnt[1][blk] = (int)((pk >> 21) & 0x1FFFFF);
            g_ccnt[2][blk] = (int)( pk >> 42);
        }
    }
}

// ---------------------------------------------------- K4: per-row scan of chunk counts
__global__ void k_scan() {
    int row = blockIdx.x;
    int t   = threadIdx.x;              // 32 threads == CBLK
    if (row == 0 && t == 0) g_sum = 0.0;
#pragma unroll
    for (int m = 0; m < 3; ++m) {
        int c = g_ccnt[m][row * CBLK + t];
        int incl = c;
#pragma unroll
        for (int d = 1; d < 32; d <<= 1) {
            int v = __shfl_up_sync(0xffffffffu, incl, d);
            if (t >= d) incl += v;
        }
        g_coff[m][row * CBLK + t] = incl - c;
        if (t == 31) g_rcnt[m][row] = incl;
    }
}

// ---------------------------------------------------------------- K5: ordered scatter
__global__ void k_scatter(const float* __restrict__ X) {
    int blk = blockIdx.x;
    int row = blk >> 5;                 // / CBLK
    int gbase = blk * CHUNK;
    int tid = threadIdx.x;
    int warp = tid >> 5, lane = tid & 31;
    unsigned lmask = (lane == 31) ? 0x7fffffffu : ((1u << lane) - 1u);
    __shared__ int wc[3][8];
    int off0 = g_coff[0][blk], off1 = g_coff[1][blk], off2 = g_coff[2][blk];
    float* d0 = g_vpos + row * L;
    float* d1 = g_vfp  + row * L;
    float* d2 = g_vneg + row * L;
    for (int it = 0; it < CHUNK / 256; ++it) {
        int g = gbase + it * 256 + tid;
        float x = X[g];
        unsigned tb = (g_tbits[g >> 5] >> (g & 31)) & 1u;
        unsigned ab = (g_abits[g >> 5] >> (g & 31)) & 1u;
        bool m0 = tb;
        bool m2 = !ab;
        bool m1 = (x > 0.f) && m2;
        unsigned b0 = __ballot_sync(0xffffffffu, m0);
        unsigned b1 = __ballot_sync(0xffffffffu, m1);
        unsigned b2 = __ballot_sync(0xffffffffu, m2);
        if (lane == 0) { wc[0][warp] = __popc(b0); wc[1][warp] = __popc(b1); wc[2][warp] = __popc(b2); }
        __syncthreads();
        int wb0 = 0, t0 = 0, wb1 = 0, t1 = 0, wb2 = 0, t2 = 0;
#pragma unroll
        for (int w = 0; w < 8; ++w) {
            int c0 = wc[0][w], c1 = wc[1][w], c2 = wc[2][w];
            if (w < warp) { wb0 += c0; wb1 += c1; wb2 += c2; }
            t0 += c0; t1 += c1; t2 += c2;
        }
        if (m0) d0[off0 + wb0 + __popc(b0 & lmask)] = x;
        if (m1) d1[off1 + wb1 + __popc(b1 & lmask)] = x;
        if (m2) d2[off2 + wb2 + __popc(b2 & lmask)] = x;
        off0 += t0; off1 += t1; off2 += t2;
        __syncthreads();
    }
}

// ---------------------------------------------------------------- K6: fused loss
__device__ __forceinline__ float softplusf(float z) {
    return fmaxf(z, 0.f) + log1pf(__expf(-fabsf(z)));
}

__global__ void k_loss(const float* __restrict__ X) {
    int blk = blockIdx.x;
    int row = blk >> 5;
    int gbase = blk * CHUNK;
    int jbase = (blk & 31) * CHUNK;     // within-row start
    int tid = threadIdx.x;
    int cp = g_rcnt[0][row], cf = g_rcnt[1][row], cn = g_rcnt[2][row];
    const float* vpos = g_vpos + row * L;
    int cF = (cf > 0) ? cf : cn;
    const float* vF = (cf > 0) ? (g_vfp + row * L) : (g_vneg + row * L);

    int mp = 0, stp = 0, mf = 0, stf = 0;
    if (cp > 0) { mp = (jbase + tid) % cp; stp = 256 % cp; }
    if (cF > 0) { mf = (jbase + tid) % cF; stf = 256 % cF; }

    float acc = 0.f;
    for (int it = 0; it < CHUNK / 256; ++it) {
        int g = gbase + it * 256 + tid;
        float x = X[g];
        float t = (float)((g_tbits[g >> 5] >> (g & 31)) & 1u);
        float dp = 5.0f, df = -5.0f;
        if (cp > 0) { dp = vpos[mp]; mp += stp; if (mp >= cp) mp -= cp; }
        if (cF > 0) { df = vF[mf];   mf += stf; if (mf >= cF) mf -= cF; }
        float sim = dp * x;
        acc += softplusf(sim) - sim * t;          // term1 (y = t)
        acc += softplusf(dp) - dp;                // term2 (y = 1)
        acc += 0.1f * softplusf(dp * df);         // alpha * term3 (y = 0)
    }
    // block reduce
    __shared__ float sh[8];
    int lane = tid & 31, warp = tid >> 5;
#pragma unroll
    for (int d = 16; d; d >>= 1) acc += __shfl_down_sync(0xffffffffu, acc, d);
    if (lane == 0) sh[warp] = acc;
    __syncthreads();
    if (warp == 0) {
        acc = (lane < 8) ? sh[lane] : 0.f;
#pragma unroll
        for (int d = 4; d; d >>= 1) acc += __shfl_down_sync(0xffffffffu, acc, d);
        if (lane == 0) atomicAdd(&g_sum, (double)acc);
    }
}

// ---------------------------------------------------------------- K7: finalize
__global__ void k_final(float* out, int n) {
    int i = blockIdx.x * 256 + threadIdx.x;
    if (i < n) out[i] = (float)(g_sum / (double)NTOT);
}

extern "C" void kernel_launch(void* const* d_in, const int* in_sizes, int n_in,
                              void* d_out, int out_size) {
    const float* X   = (const float*)d_in[0];   // input
    const float* TGT = (const float*)d_in[1];   // target
    float* out = (float*)d_out;

    k_pack   <<<NTOT / 256, 256>>>(TGT);
    k_aug    <<<NW   / 256, 256>>>();
    k_count  <<<NBLK,       256>>>(X);
    k_scan   <<<BC,          32>>>();
    k_scatter<<<NBLK,       256>>>(X);
    k_loss   <<<NBLK,       256>>>(X);
    k_final  <<<(out_size + 255) / 256, 256>>>(out, out_size);
}

// round 2
// speedup vs baseline: 1.7132x; 1.7132x over previous
#include <cuda_runtime.h>

// Geometry (fixed by reference: B=16, C=3, H=W=512)
constexpr int BC   = 48;
constexpr int HW   = 512;
constexpr int L    = HW * HW;        // 262144 px/row
constexpr int NTOT = BC * L;         // 12,582,912
constexpr int WPL  = HW / 32;        // 16 words per image line
constexpr int WPI  = HW * WPL;       // 8192 words per image
constexpr int NW   = BC * WPI;       // 393,216 mask words

constexpr int WCH  = 1024;           // pixels per warp-chunk
constexpr int NWC  = NTOT / WCH;     // 12288 warp-chunks
constexpr int CPR  = L / WCH;        // 256 warp-chunks per row
constexpr int CHUNK = 8192;          // px per block (loss)
constexpr int NBLK  = NTOT / CHUNK;  // 1536

__device__ float    g_vpos[NTOT];
__device__ float    g_vfp [NTOT];
__device__ float    g_vneg[NTOT];
__device__ unsigned g_tbits[NW];
__device__ unsigned g_xbits[NW];
__device__ unsigned g_abits[NW];
__device__ unsigned long long g_wcnt[NWC];  // packed c0|c1<<21|c2<<42
__device__ int      g_woff0[NWC], g_woff1[NWC], g_woff2[NWC];
__device__ int      g_rcnt0[BC], g_rcnt1[BC], g_rcnt2[BC];
__device__ double   g_sum;

__device__ __forceinline__ float sp_fast(float z) {
    return fmaxf(z, 0.f) + __logf(1.f + __expf(-fabsf(z)));
}

// ---------------- K1: pack t>0 and x>0 bits (reads X+TGT once, 100MB)
__global__ void k_pack(const float* __restrict__ X, const float* __restrict__ T) {
    __shared__ unsigned st[32], sx[32];
    int tid = threadIdx.x;
    if (tid < 32) { st[tid] = 0; sx[tid] = 0; }
    __syncthreads();
    int p0 = blockIdx.x * 1024 + tid * 4;
    float4 tv = *(const float4*)(T + p0);
    float4 xv = *(const float4*)(X + p0);
    unsigned tn = (tv.x>0.f) | ((tv.y>0.f)<<1) | ((tv.z>0.f)<<2) | ((tv.w>0.f)<<3);
    unsigned xn = (xv.x>0.f) | ((xv.y>0.f)<<1) | ((xv.z>0.f)<<2) | ((xv.w>0.f)<<3);
    int sh = (tid & 7) * 4;
    if (tn) atomicOr(&st[tid >> 3], tn << sh);
    if (xn) atomicOr(&sx[tid >> 3], xn << sh);
    __syncthreads();
    if (tid < 32) {
        g_tbits[blockIdx.x * 32 + tid] = st[tid];
        g_xbits[blockIdx.x * 32 + tid] = sx[tid];
    }
}

// ---------------- K2: aug = clamped 7x7 OR; per-warp-chunk counts via popc
__global__ void k_aug() {
    int wi = blockIdx.x * 256 + threadIdx.x;
    int img  = wi >> 13;
    int rem  = wi & (WPI - 1);
    int line = rem >> 4;
    int w    = rem & 15;
    const unsigned* base = g_tbits + (img << 13);
    unsigned lo = 0, mid = 0, hi = 0;
    int l0 = line - 3 < 0 ? 0 : line - 3;
    int l1 = line + 3 > HW - 1 ? HW - 1 : line + 3;
    for (int l = l0; l <= l1; ++l) {
        const unsigned* p = base + l * WPL + w;
        mid |= p[0];
        if (w > 0)       lo |= p[-1];
        if (w < WPL - 1) hi |= p[1];
    }
    unsigned out = mid;
#pragma unroll
    for (int s = 1; s <= 3; ++s) {
        out |= __funnelshift_r(mid, hi, s);
        out |= __funnelshift_l(lo, mid, s);
    }
    g_abits[wi] = out;
    unsigned na = ~out;
    unsigned long long pk = (unsigned long long)__popc(g_tbits[wi])
                          | ((unsigned long long)__popc(g_xbits[wi] & na) << 21)
                          | ((unsigned long long)__popc(na) << 42);
#pragma unroll
    for (int d = 16; d; d >>= 1) pk += __shfl_down_sync(0xffffffffu, pk, d);
    if ((threadIdx.x & 31) == 0) g_wcnt[wi >> 5] = pk;
}

// ---------------- K3: per-row exclusive scan of 256 warp-chunk counts (packed)
__global__ void k_scan() {
    int row = blockIdx.x, tid = threadIdx.x;
    if (row == 0 && tid == 0) g_sum = 0.0;
    int lane = tid & 31, wp = tid >> 5;
    unsigned long long v = g_wcnt[row * CPR + tid];
    unsigned long long incl = v;
#pragma unroll
    for (int d = 1; d < 32; d <<= 1) {
        unsigned long long t = __shfl_up_sync(0xffffffffu, incl, d);
        if (lane >= d) incl += t;
    }
    __shared__ unsigned long long wt[8];
    if (lane == 31) wt[wp] = incl;
    __syncthreads();
    unsigned long long pre = 0;
    for (int i = 0; i < wp; ++i) pre += wt[i];
    unsigned long long inclT = incl + pre;
    unsigned long long excl = inclT - v;
    const unsigned long long M = 0x1FFFFFull;
    int ci = row * CPR + tid;
    g_woff0[ci] = (int)( excl        & M);
    g_woff1[ci] = (int)((excl >> 21) & M);
    g_woff2[ci] = (int)( excl >> 42);
    if (tid == 255) {
        g_rcnt0[row] = (int)( inclT        & M);
        g_rcnt1[row] = (int)((inclT >> 21) & M);
        g_rcnt2[row] = (int)( inclT >> 42);
    }
}

// ---------------- K4: warp-local ordered scatter (no __syncthreads)
__global__ void k_scatter(const float* __restrict__ X) {
    int wp = threadIdx.x >> 5, lane = threadIdx.x & 31;
    int chunk = blockIdx.x * 8 + wp;
    int row = chunk >> 8;
    int o0 = g_woff0[chunk], o1 = g_woff1[chunk], o2 = g_woff2[chunk];
    float* d0 = g_vpos + row * L;
    float* d1 = g_vfp  + row * L;
    float* d2 = g_vneg + row * L;
    int pbase = chunk * WCH + lane * 4;
    int sh = (lane & 7) * 4;
    for (int it = 0; it < 8; ++it) {
        int p0 = pbase + it * 128;
        float4 xv = *(const float4*)(X + p0);
        int wI = p0 >> 5;
        unsigned tn  = (g_tbits[wI] >> sh) & 0xF;
        unsigned an  = (g_abits[wI] >> sh) & 0xF;
        unsigned m2n = (~an) & 0xF;
        unsigned xn  = (xv.x>0.f) | ((xv.y>0.f)<<1) | ((xv.z>0.f)<<2) | ((xv.w>0.f)<<3);
        unsigned m1n = xn & m2n;
        int pc = __popc(tn) | (__popc(m1n) << 10) | (__popc(m2n) << 20);
        int incl = pc;
#pragma unroll
        for (int d = 1; d < 32; d <<= 1) {
            int t = __shfl_up_sync(0xffffffffu, incl, d);
            if (lane >= d) incl += t;
        }
        int excl = incl - pc;
        int e0 = excl & 1023, e1 = (excl >> 10) & 1023, e2 = excl >> 20;
        float xs[4] = {xv.x, xv.y, xv.z, xv.w};
#pragma unroll
        for (int e = 0; e < 4; ++e) {
            unsigned b = 1u << e, ml = b - 1u;
            if (tn  & b) d0[o0 + e0 + __popc(tn  & ml)] = xs[e];
            if (m1n & b) d1[o1 + e1 + __popc(m1n & ml)] = xs[e];
            if (m2n & b) d2[o2 + e2 + __popc(m2n & ml)] = xs[e];
        }
        int tot = __shfl_sync(0xffffffffu, incl, 31);
        o0 += tot & 1023; o1 += (tot >> 10) & 1023; o2 += tot >> 20;
    }
}

// ---------------- K5: fused loss. term1 per-j; term2(+term3 if cF==0) per-k weighted
__global__ void k_loss(const float* __restrict__ X) {
    int blk = blockIdx.x, tid = threadIdx.x;
    int row = blk >> 5, c = blk & 31;
    int cp = g_rcnt0[row], cf = g_rcnt1[row], cn = g_rcnt2[row];
    int cF = cf > 0 ? cf : cn;
    const float* vpos = g_vpos + row * L;
    const float* vF   = (cf > 0 ? g_vfp : g_vneg) + row * L;
    bool gen = (cF > 0);   // need per-j df gather

    int jb = c * CHUNK + tid * 4;          // within-row j base
    int mp = 0, st = 0, mf = 0, stf = 0;
    if (cp > 0) { mp = jb % cp; st = 1024 % cp; }
    if (gen)    { mf = jb % cF; stf = 1024 % cF; }

    float acc = 0.f;
    int gbase = blk * CHUNK + tid * 4;
    int sh = (tid & 7) * 4;
    for (int it = 0; it < 8; ++it) {
        int g = gbase + it * 1024;
        float4 xv = *(const float4*)(X + g);
        unsigned tn = (g_tbits[g >> 5] >> sh) & 0xF;
        float xs[4] = {xv.x, xv.y, xv.z, xv.w};
#pragma unroll
        for (int e = 0; e < 4; ++e) {
            float dp = 5.f;
            if (cp > 0) { int idx = mp + e; while (idx >= cp) idx -= cp; dp = vpos[idx]; }
            float sim = dp * xs[e];
            acc += sp_fast(sim);
            if (tn & (1u << e)) acc -= sim;
            if (gen) {
                int idx = mf + e; while (idx >= cF) idx -= cF;
                acc += 0.1f * sp_fast(dp * vF[idx]);
            }
        }
        if (cp > 0) { mp += st;  if (mp >= cp) mp -= cp; }
        if (gen)    { mf += stf; if (mf >= cF) mf -= cF; }
    }

    if (cp > 0) {
        int q = L / cp, rmd = L - q * cp;
        bool fold3 = (cF == 0);
        for (int it = 0; it < 8; ++it) {
            int k0 = c * CHUNK + it * 1024 + tid * 4;
            if (k0 < cp) {
                bool v4 = (k0 + 3 < cp);
                float vv[4];
                if (v4) { float4 t4 = *(const float4*)(vpos + k0);
                          vv[0]=t4.x; vv[1]=t4.y; vv[2]=t4.z; vv[3]=t4.w; }
#pragma unroll
                for (int e = 0; e < 4; ++e) {
                    int k = k0 + e;
                    if (k < cp) {
                        float v = v4 ? vv[e] : vpos[k];
                        float w = (float)(q + (k < rmd ? 1 : 0));
                        float t = sp_fast(v) - v;
                        if (fold3) t += 0.1f * sp_fast(-5.f * v);
                        acc += w * t;
                    }
                }
            }
        }
    } else if (c == 0 && tid == 0) {
        acc += (float)L * (sp_fast(5.f) - 5.f);
        if (cF == 0) acc += 0.1f * (float)L * sp_fast(-25.f);
    }

    __shared__ float shm[8];
    int lane = tid & 31, wp = tid >> 5;
#pragma unroll
    for (int d = 16; d; d >>= 1) acc += __shfl_down_sync(0xffffffffu, acc, d);
    if (lane == 0) shm[wp] = acc;
    __syncthreads();
    if (wp == 0) {
        acc = (lane < 8) ? shm[lane] : 0.f;
#pragma unroll
        for (int d = 4; d; d >>= 1) acc += __shfl_down_sync(0xffffffffu, acc, d);
        if (lane == 0) atomicAdd(&g_sum, (double)acc);
    }
}

// ---------------- K6: finalize
__global__ void k_final(float* out, int n) {
    int i = blockIdx.x * 256 + threadIdx.x;
    if (i < n) out[i] = (float)(g_sum / (double)NTOT);
}

extern "C" void kernel_launch(void* const* d_in, const int* in_sizes, int n_in,
                              void* d_out, int out_size) {
    const float* X   = (const float*)d_in[0];
    const float* TGT = (const float*)d_in[1];
    float* out = (float*)d_out;

    k_pack   <<<NTOT / 1024, 256>>>(X, TGT);
    k_aug    <<<NW / 256,    256>>>();
    k_scan   <<<BC,          256>>>();
    k_scatter<<<NWC / 8,     256>>>(X);
    k_loss   <<<NBLK,        256>>>(X);
    k_final  <<<(out_size + 255) / 256, 256>>>(out, out_size);
}

// round 4
// speedup vs baseline: 2.8772x; 1.6794x over previous
#include <cuda_runtime.h>

// Geometry (fixed by reference: B=16, C=3, H=W=512)
constexpr int BC   = 48;
constexpr int HW   = 512;
constexpr int L    = HW * HW;        // 262144 px/row
constexpr int NTOT = BC * L;         // 12,582,912
constexpr int WPL  = HW / 32;        // 16 words per image line
constexpr int WPI  = HW * WPL;       // 8192 words per image
constexpr int NW   = BC * WPI;       // 393,216 mask words

constexpr int WCH  = 1024;           // pixels per warp-chunk
constexpr int NWC  = NTOT / WCH;     // 12288 warp-chunks
constexpr int CPR  = L / WCH;        // 256 warp-chunks per row
constexpr int CHUNK = 8192;          // px per block (loss)
constexpr int NBLK  = NTOT / CHUNK;  // 1536

__device__ float    g_vpos[NTOT];
__device__ float    g_vfp [NTOT];
__device__ float    g_vneg[NTOT];
__device__ unsigned g_tbits[NW];
__device__ unsigned g_xbits[NW];
__device__ unsigned g_abits[NW];
__device__ unsigned long long g_wcnt[NWC];  // packed c0|c1<<21|c2<<42
__device__ int      g_woff0[NWC], g_woff1[NWC], g_woff2[NWC];
__device__ int      g_rcnt0[BC], g_rcnt1[BC], g_rcnt2[BC];
__device__ double   g_sum;

__device__ __forceinline__ float sp_fast(float z) {
    return fmaxf(z, 0.f) + __logf(1.f + __expf(-fabsf(z)));
}

// ---------------- K1: pack t>0 and x>0 bits (shfl-or combine, no smem)
__global__ void k_pack(const float* __restrict__ X, const float* __restrict__ T) {
    int tid = threadIdx.x;
    int p0 = blockIdx.x * 1024 + tid * 4;
    float4 tv = *(const float4*)(T + p0);
    float4 xv = *(const float4*)(X + p0);
    unsigned tn = (tv.x>0.f) | ((tv.y>0.f)<<1) | ((tv.z>0.f)<<2) | ((tv.w>0.f)<<3);
    unsigned xn = (xv.x>0.f) | ((xv.y>0.f)<<1) | ((xv.z>0.f)<<2) | ((xv.w>0.f)<<3);
    int sh = (tid & 7) * 4;
    unsigned vt = tn << sh, vx = xn << sh;
#pragma unroll
    for (int d = 1; d < 8; d <<= 1) {
        vt |= __shfl_xor_sync(0xffffffffu, vt, d);
        vx |= __shfl_xor_sync(0xffffffffu, vx, d);
    }
    if ((tid & 7) == 0) {
        g_tbits[p0 >> 5] = vt;
        g_xbits[p0 >> 5] = vx;
    }
}

// ---------------- K2: aug = clamped 7x7 OR; per-warp-chunk counts via popc
__global__ void k_aug() {
    int wi = blockIdx.x * 256 + threadIdx.x;
    int img  = wi >> 13;
    int rem  = wi & (WPI - 1);
    int line = rem >> 4;
    int w    = rem & 15;
    const unsigned* base = g_tbits + (img << 13);
    unsigned lo = 0, mid = 0, hi = 0;
    int l0 = line - 3 < 0 ? 0 : line - 3;
    int l1 = line + 3 > HW - 1 ? HW - 1 : line + 3;
    for (int l = l0; l <= l1; ++l) {
        const unsigned* p = base + l * WPL + w;
        mid |= p[0];
        if (w > 0)       lo |= p[-1];
        if (w < WPL - 1) hi |= p[1];
    }
    unsigned out = mid;
#pragma unroll
    for (int s = 1; s <= 3; ++s) {
        out |= __funnelshift_r(mid, hi, s);
        out |= __funnelshift_l(lo, mid, s);
    }
    g_abits[wi] = out;
    unsigned na = ~out;
    unsigned long long pk = (unsigned long long)__popc(g_tbits[wi])
                          | ((unsigned long long)__popc(g_xbits[wi] & na) << 21)
                          | ((unsigned long long)__popc(na) << 42);
#pragma unroll
    for (int d = 16; d; d >>= 1) pk += __shfl_down_sync(0xffffffffu, pk, d);
    if ((threadIdx.x & 31) == 0) g_wcnt[wi >> 5] = pk;
}

// ---------------- K3: per-row exclusive scan of 256 warp-chunk counts (packed)
__global__ void k_scan() {
    int row = blockIdx.x, tid = threadIdx.x;
    if (row == 0 && tid == 0) g_sum = 0.0;
    int lane = tid & 31, wp = tid >> 5;
    unsigned long long v = g_wcnt[row * CPR + tid];
    unsigned long long incl = v;
#pragma unroll
    for (int d = 1; d < 32; d <<= 1) {
        unsigned long long t = __shfl_up_sync(0xffffffffu, incl, d);
        if (lane >= d) incl += t;
    }
    __shared__ unsigned long long wt[8];
    if (lane == 31) wt[wp] = incl;
    __syncthreads();
    unsigned long long pre = 0;
    for (int i = 0; i < wp; ++i) pre += wt[i];
    unsigned long long inclT = incl + pre;
    unsigned long long excl = inclT - v;
    const unsigned long long M = 0x1FFFFFull;
    int ci = row * CPR + tid;
    g_woff0[ci] = (int)( excl        & M);
    g_woff1[ci] = (int)((excl >> 21) & M);
    g_woff2[ci] = (int)( excl >> 42);
    if (tid == 255) {
        g_rcnt0[row] = (int)( inclT        & M);
        g_rcnt1[row] = (int)((inclT >> 21) & M);
        g_rcnt2[row] = (int)( inclT >> 42);
    }
}

// ---------------- K4: warp-local ordered scatter, ≤2 live streams
__global__ void k_scatter(const float* __restrict__ X) {
    int wp = threadIdx.x >> 5, lane = threadIdx.x & 31;
    int chunk = blockIdx.x * 8 + wp;
    int row = chunk >> 8;
    const unsigned long long M = 0x1FFFFFull;
    unsigned long long pk = g_wcnt[chunk];
    int c1 = (int)((pk >> 21) & M);
    int c2 = (int)(pk >> 42);
    bool useFp = g_rcnt1[row] > 0;      // which of vfp/vneg the loss will read
    bool s1 = useFp && (c1 > 0);        // scatter fp stream this chunk
    bool s2 = (!useFp) && (c2 > 0);     // scatter neg stream this chunk

    int o0 = g_woff0[chunk];
    float* d0 = g_vpos + row * L;
    int pbase = chunk * WCH + lane * 4;
    int sh = (lane & 7) * 4;

    if (!(s1 | s2)) {
        // fast path: only the positives stream
        for (int it = 0; it < 8; ++it) {
            int p0 = pbase + it * 128;
            float4 xv = *(const float4*)(X + p0);
            unsigned tn = (g_tbits[p0 >> 5] >> sh) & 0xF;
            int pc = __popc(tn);
            int incl = pc;
#pragma unroll
            for (int d = 1; d < 32; d <<= 1) {
                int t = __shfl_up_sync(0xffffffffu, incl, d);
                if (lane >= d) incl += t;
            }
            int e0 = incl - pc;
            float xs[4] = {xv.x, xv.y, xv.z, xv.w};
#pragma unroll
            for (int e = 0; e < 4; ++e) {
                unsigned b = 1u << e;
                if (tn & b) d0[o0 + e0 + __popc(tn & (b - 1u))] = xs[e];
            }
            o0 += __shfl_sync(0xffffffffu, incl, 31);
        }
    } else {
        int o1 = s1 ? g_woff1[chunk] : g_woff2[chunk];
        float* d1 = (s1 ? g_vfp : g_vneg) + row * L;
        for (int it = 0; it < 8; ++it) {
            int p0 = pbase + it * 128;
            float4 xv = *(const float4*)(X + p0);
            int wI = p0 >> 5;
            unsigned tn  = (g_tbits[wI] >> sh) & 0xF;
            unsigned m2n = ((~g_abits[wI]) >> sh) & 0xF;
            unsigned mn;
            if (s1) {
                unsigned xn = (xv.x>0.f) | ((xv.y>0.f)<<1) | ((xv.z>0.f)<<2) | ((xv.w>0.f)<<3);
                mn = xn & m2n;
            } else {
                mn = m2n;
            }
            int pc = __popc(tn) | (__popc(mn) << 16);
            int incl = pc;
#pragma unroll
            for (int d = 1; d < 32; d <<= 1) {
                int t = __shfl_up_sync(0xffffffffu, incl, d);
                if (lane >= d) incl += t;
            }
            int excl = incl - pc;
            int e0 = excl & 0xFFFF, e1 = excl >> 16;
            float xs[4] = {xv.x, xv.y, xv.z, xv.w};
#pragma unroll
            for (int e = 0; e < 4; ++e) {
                unsigned b = 1u << e, ml = b - 1u;
                if (tn & b) d0[o0 + e0 + __popc(tn & ml)] = xs[e];
                if (mn & b) d1[o1 + e1 + __popc(mn & ml)] = xs[e];
            }
            int tot = __shfl_sync(0xffffffffu, incl, 31);
            o0 += tot & 0xFFFF;
            o1 += tot >> 16;
        }
    }
}

// ---------------- K5: fused loss. term1 per-j; term2(+term3 if cF==0) per-k weighted
__global__ void k_loss(const float* __restrict__ X) {
    int blk = blockIdx.x, tid = threadIdx.x;
    int row = blk >> 5, c = blk & 31;
    int cp = g_rcnt0[row], cf = g_rcnt1[row], cn = g_rcnt2[row];
    int cF = cf > 0 ? cf : cn;
    const float* vpos = g_vpos + row * L;
    const float* vF   = (cf > 0 ? g_vfp : g_vneg) + row * L;
    bool gen = (cF > 0);   // need per-j df gather

    int jb = c * CHUNK + tid * 4;          // within-row j base
    int mp = 0, st = 0, mf = 0, stf = 0;
    if (cp > 0) { mp = jb % cp; st = 1024 % cp; }
    if (gen)    { mf = jb % cF; stf = 1024 % cF; }

    float acc = 0.f;
    int gbase = blk * CHUNK + tid * 4;
    int sh = (tid & 7) * 4;
    for (int it = 0; it < 8; ++it) {
        int g = gbase + it * 1024;
        float4 xv = *(const float4*)(X + g);
        unsigned tn = (g_tbits[g >> 5] >> sh) & 0xF;
        float xs[4] = {xv.x, xv.y, xv.z, xv.w};
#pragma unroll
        for (int e = 0; e < 4; ++e) {
            float dp = 5.f;
            if (cp > 0) { int idx = mp + e; idx -= (idx >= cp) ? cp : 0; dp = vpos[idx]; }
            float sim = dp * xs[e];
            acc += sp_fast(sim);
            if (tn & (1u << e)) acc -= sim;
            if (gen) {
                int idx = mf + e; idx -= (idx >= cF) ? cF : 0;
                acc += 0.1f * sp_fast(dp * vF[idx]);
            }
        }
        if (cp > 0) { mp += st;  if (mp >= cp) mp -= cp; }
        if (gen)    { mf += stf; if (mf >= cF) mf -= cF; }
    }

    if (cp > 0) {
        int q = L / cp, rmd = L - q * cp;
        bool fold3 = (cF == 0);
        for (int it = 0; it < 8; ++it) {
            int k0 = c * CHUNK + it * 1024 + tid * 4;
            if (k0 < cp) {
                bool v4 = (k0 + 3 < cp);
                float vv[4];
                if (v4) { float4 t4 = *(const float4*)(vpos + k0);
                          vv[0]=t4.x; vv[1]=t4.y; vv[2]=t4.z; vv[3]=t4.w; }
#pragma unroll
                for (int e = 0; e < 4; ++e) {
                    int k = k0 + e;
                    if (k < cp) {
                        float v = v4 ? vv[e] : vpos[k];
                        float w = (float)(q + (k < rmd ? 1 : 0));
                        float t = sp_fast(v) - v;
                        if (fold3) t += 0.1f * sp_fast(-5.f * v);
                        acc += w * t;
                    }
                }
            }
        }
    } else if (c == 0 && tid == 0) {
        acc += (float)L * (sp_fast(5.f) - 5.f);
        if (cF == 0) acc += 0.1f * (float)L * sp_fast(-25.f);
    }

    __shared__ float shm[8];
    int lane = tid & 31, wp = tid >> 5;
#pragma unroll
    for (int d = 16; d; d >>= 1) acc += __shfl_down_sync(0xffffffffu, acc, d);
    if (lane == 0) shm[wp] = acc;
    __syncthreads();
    if (wp == 0) {
        acc = (lane < 8) ? shm[lane] : 0.f;
#pragma unroll
        for (int d = 4; d; d >>= 1) acc += __shfl_down_sync(0xffffffffu, acc, d);
        if (lane == 0) atomicAdd(&g_sum, (double)acc);
    }
}

// ---------------- K6: finalize
__global__ void k_final(float* out, int n) {
    int i = blockIdx.x * 256 + threadIdx.x;
    if (i < n) out[i] = (float)(g_sum / (double)NTOT);
}

extern "C" void kernel_launch(void* const* d_in, const int* in_sizes, int n_in,
                              void* d_out, int out_size) {
    const float* X   = (const float*)d_in[0];
    const float* TGT = (const float*)d_in[1];
    float* out = (float*)d_out;

    k_pack   <<<NTOT / 1024, 256>>>(X, TGT);
    k_aug    <<<NW / 256,    256>>>();
    k_scan   <<<BC,          256>>>();
    k_scatter<<<NWC / 8,     256>>>(X);
    k_loss   <<<NBLK,        256>>>(X);
    k_final  <<<(out_size + 255) / 256, 256>>>(out, out_size);
}